// round 11
// baseline (speedup 1.0000x reference)
#include <cuda_runtime.h>
#include <cstdint>

#define BATCH   8192
#define BOX     10
#define PAIR    90          // BOX*(BOX-1)
#define NUM_OT  151
#define NUM_QT  65
#define SLICE   (NUM_OT * NUM_OT)   // 22801 floats per (qt, pair) slice
#define MAXB    512                 // safe cap on batches per qus_type (mean 126)

// ---------------- device scratch (static, no allocation) -------------------
__device__ int                g_count[NUM_QT];
__device__ int                g_slot[BATCH];
// entries[qt][slot][p] : packed {off:u32, val:f32}; [qt][slot][p] layout makes
// K2's writes coalesced (90 consecutive p per (b)).
__device__ unsigned long long g_entries[(size_t)NUM_QT * MAXB * PAIR];  // 24 MB

// ---------------------------------------------------------------------------
// K1: assign per-qt slots. Single block, smem cursors, no serial prefix.
// ---------------------------------------------------------------------------
__global__ void slot_kernel(const int* __restrict__ qus_type)
{
    __shared__ int cur[NUM_QT];
    int tid = threadIdx.x;
    if (tid < NUM_QT) cur[tid] = 0;
    __syncthreads();

    for (int b = tid; b < BATCH; b += blockDim.x) {
        int qt = __ldg(qus_type + b);
        g_slot[b] = atomicAdd(&cur[qt], 1);
    }
    __syncthreads();

    if (tid < NUM_QT) {
        int c = cur[tid];
        g_count[tid] = c < MAXB ? c : MAXB;
    }
}

// ---------------------------------------------------------------------------
// K2: packed {ol1*151+ol2, at_j*at_i} per (batch, pair), coalesced writes.
// ---------------------------------------------------------------------------
__global__ void __launch_bounds__(256)
entries_kernel(const int*   __restrict__ obj_label,   // [BATCH, BOX]
               const int*   __restrict__ qus_type,    // [BATCH]
               const float* __restrict__ attention)   // [BATCH, BOX]
{
    int t = blockIdx.x * blockDim.x + threadIdx.x;
    if (t >= BATCH * PAIR) return;

    int b = t / PAIR;
    int p = t - b * PAIR;

    int slot = g_slot[b];
    if (slot >= MAXB) return;
    int qt = __ldg(qus_type + b);

    int i  = p / (BOX - 1);
    int jj = p - i * (BOX - 1);
    int j  = jj + (jj >= i ? 1 : 0);

    int   ol1 = __ldg(obj_label + b * BOX + j);
    int   ol2 = __ldg(obj_label + b * BOX + i);
    float val = __ldg(attention + b * BOX + j) * __ldg(attention + b * BOX + i);

    unsigned int off = (unsigned)(ol1 * NUM_OT + ol2);
    unsigned long long packed =
        ((unsigned long long)off << 32) | (unsigned long long)__float_as_uint(val);

    g_entries[((size_t)qt * MAXB + (size_t)slot) * PAIR + (size_t)p] = packed;
}

// ---------------------------------------------------------------------------
// K3: fused stream-merge. One block per slice (qt, p).
//  1) zero a 91KB smem delta array
//  2) accumulate this slice's ~126 deltas via smem atomics
//  3) dst = src + delta  (pure streaming read+write; NO global atomics,
//     NO dst re-reads -> identical DRAM traffic to a bare copy)
// ---------------------------------------------------------------------------
__global__ void __launch_bounds__(512)
fused_merge_kernel(const float* __restrict__ src,
                   float*       __restrict__ out)
{
    extern __shared__ float delta[];         // SLICE floats (91204 B)

    const int slice = blockIdx.x;            // 0 .. 5849
    const int qt    = slice / PAIR;
    const int p     = slice - qt * PAIR;
    const size_t base = (size_t)slice * SLICE;

    // 1) zero delta
    for (int k = threadIdx.x; k < SLICE; k += 512)
        delta[k] = 0.0f;
    __syncthreads();

    // 2) accumulate deltas (smem atomics; collisions rare)
    const int cnt = g_count[qt];
    const unsigned long long* __restrict__ ent =
        g_entries + (size_t)qt * MAXB * PAIR + (size_t)p;
    for (int sI = threadIdx.x; sI < cnt; sI += 512) {
        unsigned long long e = __ldg(ent + (size_t)sI * PAIR);
        atomicAdd(&delta[(unsigned)(e >> 32)], __uint_as_float((unsigned)e));
    }
    __syncthreads();

    // 3) streaming copy + merge
    const float* s = src + base;
    float*       d = out + base;

    const int head = (4 - (int)(base & 3)) & 3;
    if (threadIdx.x < (unsigned)head)
        __stcs(d + threadIdx.x, __ldcs(s + threadIdx.x) + delta[threadIdx.x]);

    const int n4 = (SLICE - head) >> 2;
    const float4* __restrict__ s4 = (const float4*)(s + head);
    float4*       __restrict__ d4 = (float4*)(d + head);
    #pragma unroll 4
    for (int i = threadIdx.x; i < n4; i += 512) {
        float4 v = __ldcs(s4 + i);
        int e0 = head + (i << 2);
        v.x += delta[e0 + 0];
        v.y += delta[e0 + 1];
        v.z += delta[e0 + 2];
        v.w += delta[e0 + 3];
        __stcs(d4 + i, v);
    }

    const int tail_start = head + (n4 << 2);
    const int tail = SLICE - tail_start;     // 0..3
    if (threadIdx.x < (unsigned)tail) {
        int e = tail_start + threadIdx.x;
        __stcs(d + e, __ldcs(s + e) + delta[e]);
    }
}

// ---------------------------------------------------------------------------
// Launch: K1 -> K2 -> K3, same stream (ordered), all graph-capturable.
// ---------------------------------------------------------------------------
extern "C" void kernel_launch(void* const* d_in, const int* in_sizes, int n_in,
                              void* d_out, int out_size)
{
    const int*   obj_label    = (const int*)  d_in[0]; // [8192,10] int32
    const int*   qus_type     = (const int*)  d_in[1]; // [8192]    int32
    const float* attention    = (const float*)d_in[2]; // [8192,10] float32
    const float* score_matrix = (const float*)d_in[3]; // [65,90,151,151] float32
    float*       out          = (float*)d_out;

    static bool attr_set = false;
    if (!attr_set) {
        cudaFuncSetAttribute(fused_merge_kernel,
                             cudaFuncAttributeMaxDynamicSharedMemorySize,
                             SLICE * sizeof(float));
        attr_set = true;
    }

    slot_kernel<<<1, 1024>>>(qus_type);

    {
        int total  = BATCH * PAIR;               // 737,280
        int blocks = (total + 255) / 256;
        entries_kernel<<<blocks, 256>>>(obj_label, qus_type, attention);
    }

    fused_merge_kernel<<<NUM_QT * PAIR, 512, SLICE * sizeof(float)>>>(
        score_matrix, out);
}

// round 13
// speedup vs baseline: 1.0554x; 1.0554x over previous
#include <cuda_runtime.h>
#include <cstdint>

#define BATCH   8192
#define BOX     10
#define PAIR    90                  // BOX*(BOX-1)
#define NUM_OT  151
#define NUM_QT  65
#define SLICE   (NUM_OT * NUM_OT)   // 22801 floats per (qt, pair) slice
#define NSLICE  (NUM_QT * PAIR)     // 5850
#define MAXB    512                 // cap on batches per qus_type (mean 126)
#define LAG     1184                // one resident wave (148 SMs x 8 blocks)

// ---------------- device scratch (static, no allocation) -------------------
__device__ int                g_epoch = 0;
__device__ int                g_count[NUM_QT];
__device__ int                g_flag[NSLICE];            // epoch-tagged
__device__ unsigned long long g_entries[(size_t)NUM_QT * MAXB * PAIR]; // 24 MB

// ---------------------------------------------------------------------------
// K0: bump epoch, zero bucket counters. Tiny.
// ---------------------------------------------------------------------------
__global__ void prep_kernel()
{
    if (threadIdx.x == 0) g_epoch = g_epoch + 1;
    if (threadIdx.x < NUM_QT) g_count[threadIdx.x] = 0;
}

// ---------------------------------------------------------------------------
// K1: one thread per batch: grab a slot in its qt bucket, emit 90 packed
// {off = ol1*151+ol2, val = at_j*at_i} entries (contiguous 720B write).
// ---------------------------------------------------------------------------
__global__ void __launch_bounds__(256)
entries_kernel(const int*   __restrict__ obj_label,   // [BATCH, BOX]
               const int*   __restrict__ qus_type,    // [BATCH]
               const float* __restrict__ attention)   // [BATCH, BOX]
{
    int b = blockIdx.x * blockDim.x + threadIdx.x;
    if (b >= BATCH) return;

    int qt   = __ldg(qus_type + b);
    int slot = atomicAdd(&g_count[qt], 1);
    if (slot >= MAXB) return;

    int   lab[BOX];
    float att[BOX];
    #pragma unroll
    for (int k = 0; k < BOX; k++) {
        lab[k] = __ldg(obj_label + b * BOX + k);
        att[k] = __ldg(attention + b * BOX + k);
    }

    unsigned long long* dst = g_entries + ((size_t)qt * MAXB + slot) * PAIR;
    #pragma unroll
    for (int i = 0; i < BOX; i++) {
        #pragma unroll
        for (int jj = 0; jj < BOX - 1; jj++) {
            int j = jj + (jj >= i ? 1 : 0);        // all j != i, ascending
            unsigned int off = (unsigned)(lab[j] * NUM_OT + lab[i]);
            float        val = att[j] * att[i];
            dst[i * (BOX - 1) + jj] =
                ((unsigned long long)off << 32) |
                (unsigned long long)__float_as_uint(val);
        }
    }
}

// ---------------------------------------------------------------------------
// K2: pipelined copy + lagged scatter in one grid.
//   block b < NSLICE:  copy slice b (pure 3-instr inner loop), publish flag.
//   block b >= LAG:    wait flag[b-LAG] (virtually always set), then apply
//                      that slice's ~126 atomics -> L2-hot lines, overlapped
//                      with the rest of the grid's streaming copy.
// Deadlock-free: a block only waits on earlier-dispatched blocks (induction
// bottoms out at b < LAG, which never wait). Replay-safe via epoch tags.
// ---------------------------------------------------------------------------
__global__ void __launch_bounds__(256, 8)
copy_scatter_pipeline_kernel(const float* __restrict__ src,
                             float*       __restrict__ out)
{
    const int b = blockIdx.x;
    const int epoch = *(volatile int*)&g_epoch;

    if (b < NSLICE) {
        // ---- copy slice b ----
        const size_t base = (size_t)b * SLICE;
        const float* s = src + base;
        float*       d = out + base;

        const int head = (4 - (int)(base & 3)) & 3;
        if (threadIdx.x < (unsigned)head)
            d[threadIdx.x] = __ldcs(s + threadIdx.x);

        const int n4 = (SLICE - head) >> 2;
        const float4* __restrict__ s4 = (const float4*)(s + head);
        float4*       __restrict__ d4 = (float4*)(d + head);
        #pragma unroll 4
        for (int i = threadIdx.x; i < n4; i += 256)
            d4[i] = __ldcs(s4 + i);          // default WB store: stays in L2

        const int ts   = head + (n4 << 2);
        const int tail = SLICE - ts;         // 0..3
        if (threadIdx.x < (unsigned)tail)
            d[ts + threadIdx.x] = __ldcs(s + ts + threadIdx.x);

        // publish: all threads fence their stores, then one sets the flag
        __threadfence();
        __syncthreads();
        if (threadIdx.x == 0)
            atomicExch(&g_flag[b], epoch);
    }

    if (b >= LAG) {
        // ---- scatter for slice (b - LAG), copied ~one wave ago ----
        const int t = b - LAG;
        if (threadIdx.x == 0) {
            while (atomicAdd(&g_flag[t], 0) != epoch)
                __nanosleep(64);
        }
        __syncthreads();
        __threadfence();

        const int qt = t / PAIR;
        const int p  = t - qt * PAIR;
        int cnt = g_count[qt];
        if (cnt > MAXB) cnt = MAXB;

        float* d = out + (size_t)t * SLICE;
        const unsigned long long* __restrict__ ent =
            g_entries + (size_t)qt * MAXB * PAIR + (size_t)p;

        for (int k = threadIdx.x; k < cnt; k += 256) {
            unsigned long long e = __ldg(ent + (size_t)k * PAIR);
            atomicAdd(d + (unsigned)(e >> 32), __uint_as_float((unsigned)e));
        }
    }
}

// ---------------------------------------------------------------------------
// Launch: K0 -> K1 -> K2, same stream (ordered), all graph-capturable.
// ---------------------------------------------------------------------------
extern "C" void kernel_launch(void* const* d_in, const int* in_sizes, int n_in,
                              void* d_out, int out_size)
{
    const int*   obj_label    = (const int*)  d_in[0]; // [8192,10] int32
    const int*   qus_type     = (const int*)  d_in[1]; // [8192]    int32
    const float* attention    = (const float*)d_in[2]; // [8192,10] float32
    const float* score_matrix = (const float*)d_in[3]; // [65,90,151,151] float32
    float*       out          = (float*)d_out;

    prep_kernel<<<1, 128>>>();

    entries_kernel<<<(BATCH + 255) / 256, 256>>>(obj_label, qus_type, attention);

    copy_scatter_pipeline_kernel<<<NSLICE + LAG, 256>>>(score_matrix, out);
}